// round 4
// baseline (speedup 1.0000x reference)
#include <cuda_runtime.h>
#include <cuda_bf16.h>

// x: (8, 320, 128, 128) fp32, out same.
// out(c,p) = (silu(x[S(p)]) + x[p]) * (sigmoid(silu(x[S2(p)])) - 0.5)
// S per channel: c%5==0: j+1 ; 1: j-1 ; 2: i+1 ; 3: i-1 ; 4: identity (circular)

#define HH 128
#define WW 128
#define PLANE (HH*WW)
#define NCH 320
#define NGROUPS (8*NCH*(HH/4))   // warp = 4 rows; 81920 groups

__device__ __forceinline__ float tanhapx(float a) {
    float r;
    asm("tanh.approx.f32 %0, %1;" : "=f"(r) : "f"(a));
    return r;
}
// silu(a) = 0.5a*tanh(0.5a) + 0.5a        (1 MUFU)
__device__ __forceinline__ float silu_f(float a) {
    float h = 0.5f * a;
    return fmaf(h, tanhapx(h), h);
}
// sigmoid(a) - 0.5 = 0.5*tanh(0.5a)       (1 MUFU)
__device__ __forceinline__ float fatt_f(float a) {
    return 0.5f * tanhapx(0.5f * a);
}
__device__ __forceinline__ float4 silu4(float4 v) {
    return make_float4(silu_f(v.x), silu_f(v.y), silu_f(v.z), silu_f(v.w));
}
// (f1 + x0) * fatt(f2), componentwise
__device__ __forceinline__ float4 comb4(float4 x0, float4 f1, float4 f2) {
    return make_float4((f1.x + x0.x) * fatt_f(f2.x),
                       (f1.y + x0.y) * fatt_f(f2.y),
                       (f1.z + x0.z) * fatt_f(f2.z),
                       (f1.w + x0.w) * fatt_f(f2.w));
}

__global__ __launch_bounds__(256, 8)
void ablock_kernel(const float* __restrict__ x, float* __restrict__ out) {
    const int lane = threadIdx.x & 31;
    const int wrp  = threadIdx.x >> 5;
    const int g    = blockIdx.x * 8 + wrp;          // < 81920
    const int i0   = (g & 31) << 2;                 // first of 4 rows
    const int bc   = g >> 5;                        // plane index
    const int s    = bc % 5;                        // == c%5 since 5|320
    const float* plane = x   + (long long)bc * PLANE;
    float*      oplane = out + (long long)bc * PLANE;
    const int j0 = lane << 2;

    if (s == 0) {
        // S: j+1
        #pragma unroll
        for (int t = 0; t < 4; t++) {
            const float* row = plane + (i0 + t) * WW;
            float4 a = *(const float4*)(row + j0);
            float4 b = *(const float4*)(row + ((j0 + 4) & 127));
            float s1 = silu_f(a.y), s2 = silu_f(a.z), s3 = silu_f(a.w);
            float s4 = silu_f(b.x), s5 = silu_f(b.y);
            float4 r;
            r.x = (s1 + a.x) * fatt_f(s2);
            r.y = (s2 + a.y) * fatt_f(s3);
            r.z = (s3 + a.z) * fatt_f(s4);
            r.w = (s4 + a.w) * fatt_f(s5);
            __stcs((float4*)(oplane + (i0 + t) * WW + j0), r);
        }
    } else if (s == 1) {
        // S: j-1
        #pragma unroll
        for (int t = 0; t < 4; t++) {
            const float* row = plane + (i0 + t) * WW;
            float4 a = *(const float4*)(row + j0);
            float4 b = *(const float4*)(row + ((j0 + 124) & 127));
            float s0 = silu_f(b.z), s1 = silu_f(b.w), s2 = silu_f(a.x);
            float s3 = silu_f(a.y), s4 = silu_f(a.z);
            float4 r;
            r.x = (s1 + a.x) * fatt_f(s0);
            r.y = (s2 + a.y) * fatt_f(s1);
            r.z = (s3 + a.z) * fatt_f(s2);
            r.w = (s4 + a.w) * fatt_f(s3);
            __stcs((float4*)(oplane + (i0 + t) * WW + j0), r);
        }
    } else if (s == 2) {
        // S: i+1. rows i0 .. i0+5, all loads issued up front (MLP=6)
        float4 v0 = *(const float4*)(plane + ((i0 + 0) & 127) * WW + j0);
        float4 v1 = *(const float4*)(plane + ((i0 + 1) & 127) * WW + j0);
        float4 v2 = *(const float4*)(plane + ((i0 + 2) & 127) * WW + j0);
        float4 v3 = *(const float4*)(plane + ((i0 + 3) & 127) * WW + j0);
        float4 v4 = *(const float4*)(plane + ((i0 + 4) & 127) * WW + j0);
        float4 v5 = *(const float4*)(plane + ((i0 + 5) & 127) * WW + j0);
        float4 s1 = silu4(v1), s2v = silu4(v2), s3 = silu4(v3);
        float4 s4 = silu4(v4), s5 = silu4(v5);
        __stcs((float4*)(oplane + (i0 + 0) * WW + j0), comb4(v0, s1, s2v));
        __stcs((float4*)(oplane + (i0 + 1) * WW + j0), comb4(v1, s2v, s3));
        __stcs((float4*)(oplane + (i0 + 2) * WW + j0), comb4(v2, s3, s4));
        __stcs((float4*)(oplane + (i0 + 3) * WW + j0), comb4(v3, s4, s5));
    } else if (s == 3) {
        // S: i-1. rows i0-2 .. i0+3, all loads issued up front (MLP=6)
        float4 m2 = *(const float4*)(plane + ((i0 + 126) & 127) * WW + j0);
        float4 m1 = *(const float4*)(plane + ((i0 + 127) & 127) * WW + j0);
        float4 v0 = *(const float4*)(plane + ((i0 + 0) & 127) * WW + j0);
        float4 v1 = *(const float4*)(plane + ((i0 + 1) & 127) * WW + j0);
        float4 v2 = *(const float4*)(plane + ((i0 + 2) & 127) * WW + j0);
        float4 v3 = *(const float4*)(plane + ((i0 + 3) & 127) * WW + j0);
        float4 sm2 = silu4(m2), sm1 = silu4(m1), s0 = silu4(v0);
        float4 s1 = silu4(v1), s2v = silu4(v2);
        __stcs((float4*)(oplane + (i0 + 0) * WW + j0), comb4(v0, sm1, sm2));
        __stcs((float4*)(oplane + (i0 + 1) * WW + j0), comb4(v1, s0, sm1));
        __stcs((float4*)(oplane + (i0 + 2) * WW + j0), comb4(v2, s1, s0));
        __stcs((float4*)(oplane + (i0 + 3) * WW + j0), comb4(v3, s2v, s1));
    } else {
        // identity: f1 = f2 = silu(a)
        #pragma unroll
        for (int t = 0; t < 4; t++) {
            const float* row = plane + (i0 + t) * WW;
            float4 a = *(const float4*)(row + j0);
            float4 f = silu4(a);
            __stcs((float4*)(oplane + (i0 + t) * WW + j0), comb4(a, f, f));
        }
    }
}

extern "C" void kernel_launch(void* const* d_in, const int* in_sizes, int n_in,
                              void* d_out, int out_size) {
    const float* x = (const float*)d_in[0];
    float* out = (float*)d_out;
    dim3 grid(NGROUPS / 8);   // 10240 blocks
    dim3 block(256);
    ablock_kernel<<<grid, block>>>(x, out);
}

// round 5
// speedup vs baseline: 1.0197x; 1.0197x over previous
#include <cuda_runtime.h>
#include <cuda_bf16.h>

// x: (8, 320, 128, 128) fp32, out same.
// out(c,p) = (silu(x[S(p)]) + x[p]) * (sigmoid(silu(x[S2(p)])) - 0.5)
// S per channel: c%5==0: j+1 ; 1: j-1 ; 2: i+1 ; 3: i-1 ; 4: identity (circular)

#define HH 128
#define WW 128
#define PLANE (HH*WW)
#define NCH 320
#define NGROUPS (8*NCH*(HH/4))   // warp = 4 rows; 81920 groups

__device__ __forceinline__ float tanhapx(float a) {
    float r;
    asm("tanh.approx.f32 %0, %1;" : "=f"(r) : "f"(a));
    return r;
}
// silu(a) = 0.5a*tanh(0.5a) + 0.5a        (1 MUFU)
__device__ __forceinline__ float silu_f(float a) {
    float h = 0.5f * a;
    return fmaf(h, tanhapx(h), h);
}
// sigmoid(a) - 0.5 = 0.5*tanh(0.5a)       (1 MUFU)
__device__ __forceinline__ float fatt_f(float a) {
    return 0.5f * tanhapx(0.5f * a);
}
__device__ __forceinline__ float4 silu4(float4 v) {
    return make_float4(silu_f(v.x), silu_f(v.y), silu_f(v.z), silu_f(v.w));
}
// (f1 + x0) * fatt(f2), componentwise
__device__ __forceinline__ float4 comb4(float4 x0, float4 f1, float4 f2) {
    return make_float4((f1.x + x0.x) * fatt_f(f2.x),
                       (f1.y + x0.y) * fatt_f(f2.y),
                       (f1.z + x0.z) * fatt_f(f2.z),
                       (f1.w + x0.w) * fatt_f(f2.w));
}

__global__ __launch_bounds__(256, 8)
void ablock_kernel(const float* __restrict__ x, float* __restrict__ out) {
    const int lane = threadIdx.x & 31;
    const int wrp  = threadIdx.x >> 5;
    const int g    = blockIdx.x * 8 + wrp;          // < 81920
    const int i0   = (g & 31) << 2;                 // first of 4 rows
    const int bc   = g >> 5;                        // plane index
    const int s    = bc % 5;                        // == c%5 since 5|320
    const float* plane = x   + (long long)bc * PLANE;
    float*      oplane = out + (long long)bc * PLANE;
    const int j0 = lane << 2;

    if (s == 0) {
        // S: j+1. neighbors j0+4, j0+5 come from lane+1 via shuffle (circular)
        #pragma unroll
        for (int t = 0; t < 4; t++) {
            const float* row = plane + (i0 + t) * WW;
            float4 a = *(const float4*)(row + j0);
            float bx = __shfl_sync(0xffffffffu, a.x, lane + 1, 32);
            float by = __shfl_sync(0xffffffffu, a.y, lane + 1, 32);
            float s1 = silu_f(a.y), s2 = silu_f(a.z), s3 = silu_f(a.w);
            float s4 = silu_f(bx),  s5 = silu_f(by);
            float4 r;
            r.x = (s1 + a.x) * fatt_f(s2);
            r.y = (s2 + a.y) * fatt_f(s3);
            r.z = (s3 + a.z) * fatt_f(s4);
            r.w = (s4 + a.w) * fatt_f(s5);
            *(float4*)(oplane + (i0 + t) * WW + j0) = r;
        }
    } else if (s == 1) {
        // S: j-1. neighbors j0-1, j0-2 come from lane-1 via shuffle (circular)
        #pragma unroll
        for (int t = 0; t < 4; t++) {
            const float* row = plane + (i0 + t) * WW;
            float4 a = *(const float4*)(row + j0);
            float bw = __shfl_sync(0xffffffffu, a.w, lane + 31, 32);
            float bz = __shfl_sync(0xffffffffu, a.z, lane + 31, 32);
            float s0 = silu_f(bz), s1 = silu_f(bw), s2 = silu_f(a.x);
            float s3 = silu_f(a.y), s4 = silu_f(a.z);
            float4 r;
            r.x = (s1 + a.x) * fatt_f(s0);
            r.y = (s2 + a.y) * fatt_f(s1);
            r.z = (s3 + a.z) * fatt_f(s2);
            r.w = (s4 + a.w) * fatt_f(s3);
            *(float4*)(oplane + (i0 + t) * WW + j0) = r;
        }
    } else if (s == 2) {
        // S: i+1. rows i0 .. i0+5, loads front-batched (MLP=6)
        float4 v0 = *(const float4*)(plane + ((i0 + 0) & 127) * WW + j0);
        float4 v1 = *(const float4*)(plane + ((i0 + 1) & 127) * WW + j0);
        float4 v2 = *(const float4*)(plane + ((i0 + 2) & 127) * WW + j0);
        float4 v3 = *(const float4*)(plane + ((i0 + 3) & 127) * WW + j0);
        float4 v4 = *(const float4*)(plane + ((i0 + 4) & 127) * WW + j0);
        float4 v5 = *(const float4*)(plane + ((i0 + 5) & 127) * WW + j0);
        float4 s1 = silu4(v1), s2v = silu4(v2), s3 = silu4(v3);
        float4 s4 = silu4(v4), s5 = silu4(v5);
        *(float4*)(oplane + (i0 + 0) * WW + j0) = comb4(v0, s1, s2v);
        *(float4*)(oplane + (i0 + 1) * WW + j0) = comb4(v1, s2v, s3);
        *(float4*)(oplane + (i0 + 2) * WW + j0) = comb4(v2, s3, s4);
        *(float4*)(oplane + (i0 + 3) * WW + j0) = comb4(v3, s4, s5);
    } else if (s == 3) {
        // S: i-1. rows i0-2 .. i0+3, loads front-batched (MLP=6)
        float4 m2 = *(const float4*)(plane + ((i0 + 126) & 127) * WW + j0);
        float4 m1 = *(const float4*)(plane + ((i0 + 127) & 127) * WW + j0);
        float4 v0 = *(const float4*)(plane + ((i0 + 0) & 127) * WW + j0);
        float4 v1 = *(const float4*)(plane + ((i0 + 1) & 127) * WW + j0);
        float4 v2 = *(const float4*)(plane + ((i0 + 2) & 127) * WW + j0);
        float4 v3 = *(const float4*)(plane + ((i0 + 3) & 127) * WW + j0);
        float4 sm2 = silu4(m2), sm1 = silu4(m1), s0 = silu4(v0);
        float4 s1 = silu4(v1), s2v = silu4(v2);
        *(float4*)(oplane + (i0 + 0) * WW + j0) = comb4(v0, sm1, sm2);
        *(float4*)(oplane + (i0 + 1) * WW + j0) = comb4(v1, s0, sm1);
        *(float4*)(oplane + (i0 + 2) * WW + j0) = comb4(v2, s1, s0);
        *(float4*)(oplane + (i0 + 3) * WW + j0) = comb4(v3, s2v, s1);
    } else {
        // identity: f1 = f2 = silu(a)
        #pragma unroll
        for (int t = 0; t < 4; t++) {
            const float* row = plane + (i0 + t) * WW;
            float4 a = *(const float4*)(row + j0);
            float4 f = silu4(a);
            *(float4*)(oplane + (i0 + t) * WW + j0) = comb4(a, f, f);
        }
    }
}

extern "C" void kernel_launch(void* const* d_in, const int* in_sizes, int n_in,
                              void* d_out, int out_size) {
    const float* x = (const float*)d_in[0];
    float* out = (float*)d_out;
    dim3 grid(NGROUPS / 8);   // 10240 blocks
    dim3 block(256);
    ablock_kernel<<<grid, block>>>(x, out);
}